// round 11
// baseline (speedup 1.0000x reference)
#include <cuda_runtime.h>

// FraudDetectionModel R11: single graph node, NO smem, NO barrier, NO fold.
//  Discriminating experiment: every 32.2us kernel (R2/R3) was barrier-free
//  with LDC params; every 34.4us kernel had smem params + __syncthreads,
//  invariant to L1%, occupancy, prologue parallelism. Theory: the barrier
//  extends every CTA's lifetime by the param-LDG round trip (~6% of CTA
//  life = the 67%->62% DRAM gap). Here each thread loads raw params itself
//  via 12 vectorized uniform __ldg (broadcast, L1-hot, nL=1; R1's mistake
//  was 40 SCALAR loads) and computes the original math -- warps fully
//  decoupled.

#define BATCH   16777216
#define THREADS 256
#define ROWS_PER_THREAD 4

__device__ __forceinline__ float fast_tanh(float x) {
    float y;
    asm("tanh.approx.f32 %0, %1;" : "=f"(y) : "f"(x));
    return y;
}

__global__ void __launch_bounds__(THREADS, 6)
fraud_mlp_kernel(const float4* __restrict__ x,    // [B/2] row pairs
                 float4*       __restrict__ out,  // [B/4] quad outputs
                 const float4* __restrict__ Ws4,  // [4] = Ws[4,2,2]
                 const float4* __restrict__ bs4,  // [2] = bs[4,2]
                 const float4* __restrict__ sc4,  // [2] = scales[4,2]
                 const float4* __restrict__ sh4,  // [2] = shifts[4,2]
                 const float2* __restrict__ Wf2,  // [1] = Wf[1,2]
                 const float*  __restrict__ bf)   // [1]
{
    const int i = blockIdx.x * blockDim.x + threadIdx.x;

    // Data loads first (front-batched with the param loads below).
    const float4 xv0 = x[2 * i + 0];   // rows 0,1
    const float4 xv1 = x[2 * i + 1];   // rows 2,3

    // 12 uniform-address vector loads: all broadcast, L1-resident after warm.
    const float4 w0 = __ldg(Ws4 + 0);          // layer0: w00 w01 w10 w11
    const float4 w1 = __ldg(Ws4 + 1);
    const float4 w2 = __ldg(Ws4 + 2);
    const float4 w3 = __ldg(Ws4 + 3);
    const float4 b01 = __ldg(bs4 + 0);         // b0(2), b1(2)
    const float4 b23 = __ldg(bs4 + 1);
    const float4 s01 = __ldg(sc4 + 0);
    const float4 s23 = __ldg(sc4 + 1);
    const float4 t01 = __ldg(sh4 + 0);
    const float4 t23 = __ldg(sh4 + 1);
    const float2 wf  = __ldg(Wf2);
    const float  bff = __ldg(bf);

    float ha[4], hb[4];
    ha[0] = xv0.x; hb[0] = xv0.y;  ha[1] = xv0.z; hb[1] = xv0.w;
    ha[2] = xv1.x; hb[2] = xv1.y;  ha[3] = xv1.z; hb[3] = xv1.w;

    // original math: h <- tanh(W h + b) * s + t, fully unrolled
#pragma unroll
    for (int r = 0; r < 4; r++) {
        float u0, u1;
        // layer 0
        u0 = fmaf(w0.x, ha[r], fmaf(w0.y, hb[r], b01.x));
        u1 = fmaf(w0.z, ha[r], fmaf(w0.w, hb[r], b01.y));
        ha[r] = fmaf(fast_tanh(u0), s01.x, t01.x);
        hb[r] = fmaf(fast_tanh(u1), s01.y, t01.y);
        // layer 1
        u0 = fmaf(w1.x, ha[r], fmaf(w1.y, hb[r], b01.z));
        u1 = fmaf(w1.z, ha[r], fmaf(w1.w, hb[r], b01.w));
        ha[r] = fmaf(fast_tanh(u0), s01.z, t01.z);
        hb[r] = fmaf(fast_tanh(u1), s01.w, t01.w);
        // layer 2
        u0 = fmaf(w2.x, ha[r], fmaf(w2.y, hb[r], b23.x));
        u1 = fmaf(w2.z, ha[r], fmaf(w2.w, hb[r], b23.y));
        ha[r] = fmaf(fast_tanh(u0), s23.x, t23.x);
        hb[r] = fmaf(fast_tanh(u1), s23.y, t23.y);
        // layer 3
        u0 = fmaf(w3.x, ha[r], fmaf(w3.y, hb[r], b23.z));
        u1 = fmaf(w3.z, ha[r], fmaf(w3.w, hb[r], b23.w));
        ha[r] = fmaf(fast_tanh(u0), s23.z, t23.z);
        hb[r] = fmaf(fast_tanh(u1), s23.w, t23.w);
    }

    float4 o;
    o.x = fmaf(wf.x, ha[0], fmaf(wf.y, hb[0], bff));
    o.y = fmaf(wf.x, ha[1], fmaf(wf.y, hb[1], bff));
    o.z = fmaf(wf.x, ha[2], fmaf(wf.y, hb[2], bff));
    o.w = fmaf(wf.x, ha[3], fmaf(wf.y, hb[3], bff));

    out[i] = o;
}

extern "C" void kernel_launch(void* const* d_in, const int* in_sizes, int n_in,
                              void* d_out, int out_size)
{
    const float4* x = (const float4*)d_in[0];
    float4* out = (float4*)d_out;

    const int nthreads = BATCH / ROWS_PER_THREAD;   // 4,194,304
    const int blocks = nthreads / THREADS;          // 16384
    fraud_mlp_kernel<<<blocks, THREADS>>>(
        x, out,
        (const float4*)d_in[1], (const float4*)d_in[2], (const float4*)d_in[3],
        (const float4*)d_in[4], (const float2*)d_in[5], (const float*)d_in[6]);
}

// round 12
// speedup vs baseline: 1.0912x; 1.0912x over previous
#include <cuda_runtime.h>

// FraudDetectionModel R12: 2 graph nodes, constant-bank params, no memcpy.
//  11-round synthesis: every param path through L1tex (LDG or LDS) costs
//  ~2.2us vs the constant-port (LDC) kernels R2/R3 which run at the 32.2us
//  HBM floor. LDC is a separate port; the data stream keeps all of L1tex.
//  Trick: __constant__ symbols are backed by device memory; a fold kernel
//  STGs folded params into the symbol's backing store (cudaGetSymbolAddress),
//  and the constant cache is invalidated at the next kernel-launch boundary.
//  Node 1: 1-warp lane-parallel fold -> c_fold backing store.
//  Node 2: R2-shaped main kernel, folded math, LDC params, 4 rows/thread.

#define BATCH   16777216
#define THREADS 256
#define ROWS_PER_THREAD 4

// Folded params: layer l (0..3) at [6l]: w00 w01 w10 w11 b0 b1 ; [24..26] wf0 wf1 bf
__constant__ float c_fold[28];

__device__ __forceinline__ float fast_tanh(float x) {
    float y;
    asm("tanh.approx.f32 %0, %1;" : "=f"(y) : "f"(x));
    return y;
}

// Lane-parallel fold: one folded param per lane, written straight into the
// constant symbol's backing store.
__global__ void fold_params_kernel(float* __restrict__ dst,          // = &c_fold backing
                                   const float* __restrict__ Ws,     // [4,2,2]
                                   const float* __restrict__ bs,     // [4,2]
                                   const float* __restrict__ sc,     // [4,2]
                                   const float* __restrict__ sh,     // [4,2]
                                   const float* __restrict__ Wf,     // [1,2]
                                   const float* __restrict__ bf)     // [1]
{
    const int t = threadIdx.x;
    if (t >= 27) return;

    float v;
    if (t < 24) {
        const int l = t / 6;          // layer
        const int j = t % 6;          // 0..3 W, 4..5 bias
        if (l == 0) {
            v = (j < 4) ? Ws[j] : bs[j - 4];
        } else if (j < 4) {
            // W'_l[j] = W_l[j] * s_{l-1}[col(j)]
            v = Ws[l * 4 + j] * sc[(l - 1) * 2 + (j & 1)];
        } else {
            // b'_l[row] = W_l[row,:].t_{l-1} + b_l[row]
            const int row = j - 4;
            v = fmaf(Ws[l * 4 + row * 2 + 0], sh[(l - 1) * 2 + 0],
                fmaf(Ws[l * 4 + row * 2 + 1], sh[(l - 1) * 2 + 1],
                     bs[l * 2 + row]));
        }
    } else if (t == 24) {
        v = Wf[0] * sc[6];                                   // wf0'
    } else if (t == 25) {
        v = Wf[1] * sc[7];                                   // wf1'
    } else {
        v = fmaf(Wf[0], sh[6], fmaf(Wf[1], sh[7], bf[0]));   // bf'
    }
    dst[t] = v;
}

__global__ void __launch_bounds__(THREADS)
fraud_mlp_kernel(const float4* __restrict__ x,    // [B/2] row pairs
                 float4*       __restrict__ out)  // [B/4] quad outputs
{
    const int i = blockIdx.x * blockDim.x + threadIdx.x;

    const float4 xv0 = x[2 * i + 0];   // rows 0,1
    const float4 xv1 = x[2 * i + 1];   // rows 2,3

    float ha[4], hb[4];
    ha[0] = xv0.x; hb[0] = xv0.y;  ha[1] = xv0.z; hb[1] = xv0.w;
    ha[2] = xv1.x; hb[2] = xv1.y;  ha[3] = xv1.z; hb[3] = xv1.w;

    // folded chain: h <- tanh(W' h + b'), all params via LDC (literal offsets)
#pragma unroll
    for (int l = 0; l < 4; l++) {
        const float w00 = c_fold[l * 6 + 0], w01 = c_fold[l * 6 + 1];
        const float w10 = c_fold[l * 6 + 2], w11 = c_fold[l * 6 + 3];
        const float b0  = c_fold[l * 6 + 4], b1  = c_fold[l * 6 + 5];
#pragma unroll
        for (int r = 0; r < 4; r++) {
            float u0 = fmaf(w00, ha[r], fmaf(w01, hb[r], b0));
            float u1 = fmaf(w10, ha[r], fmaf(w11, hb[r], b1));
            ha[r] = fast_tanh(u0);
            hb[r] = fast_tanh(u1);
        }
    }

    const float wf0 = c_fold[24], wf1 = c_fold[25], bff = c_fold[26];

    float4 o;
    o.x = fmaf(wf0, ha[0], fmaf(wf1, hb[0], bff));
    o.y = fmaf(wf0, ha[1], fmaf(wf1, hb[1], bff));
    o.z = fmaf(wf0, ha[2], fmaf(wf1, hb[2], bff));
    o.w = fmaf(wf0, ha[3], fmaf(wf1, hb[3], bff));

    out[i] = o;
}

extern "C" void kernel_launch(void* const* d_in, const int* in_sizes, int n_in,
                              void* d_out, int out_size)
{
    const float4* x = (const float4*)d_in[0];
    float4* out = (float4*)d_out;

    // Writable backing store of the __constant__ symbol.
    void* c_addr = nullptr;
    cudaGetSymbolAddress(&c_addr, c_fold);

    fold_params_kernel<<<1, 32>>>(
        (float*)c_addr,
        (const float*)d_in[1], (const float*)d_in[2], (const float*)d_in[3],
        (const float*)d_in[4], (const float*)d_in[5], (const float*)d_in[6]);

    const int nthreads = BATCH / ROWS_PER_THREAD;   // 4,194,304
    const int blocks = nthreads / THREADS;          // 16384
    fraud_mlp_kernel<<<blocks, THREADS>>>(x, out);
}